// round 17
// baseline (speedup 1.0000x reference)
#include <cuda_runtime.h>
#include <cstdint>
#include <cstddef>

// Problem constants
constexpr int T   = 50;
constexpr int B   = 512;
constexpr int IN  = 784;
constexpr int KPAD = 800;           // slices padded to 800 (25 x k32 chunks)
constexpr int H   = 800;
constexpr int OUT = 10;
constexpr int MROWS = T * B;        // 25600
constexpr int BH    = B * H;        // 409600
constexpr int BO    = B * OUT;      // 5120

constexpr int NSLICE = 5;           // 7-bit slices per fp32
constexpr int NCHUNK = KPAD / 32;   // 25

#define BETA 0.95f

// Scratch (static device globals; no runtime allocation)
__device__ float  g_x1[(size_t)T * BH];                  // x @ W1^T   (82 MB)
__device__ float  g_z2[(size_t)T * BH];                  // spk1 @ W2^T(82 MB)
__device__ float  g_z3[(size_t)T * BO];                  // spk2 @ W3^T(1 MB)
__device__ int8_t g_sx[(size_t)NSLICE * MROWS * KPAD];   // x slices (102 MB)
__device__ int8_t g_sw[(size_t)NSLICE * H * KPAD];       // W1 slices (3.2 MB)
__device__ float  g_su[MROWS];                           // per-row scale 2^(e-6)
__device__ float  g_sv[H];

// ---------------------------------------------------------------------------
// Row slicing (R14-R16 PROVEN exact): m = row max|x|, e = ilogb(m)+1;
// slice s = rint(resid / 2^(e-6-7s)), |slice| <= 64; exact FMA residual.
// ---------------------------------------------------------------------------
__global__ void __launch_bounds__(256)
slice_rows(const float* __restrict__ X, int8_t* __restrict__ S,
           float* __restrict__ scale, int cols, size_t plane)
{
    const int row = blockIdx.x;
    const int tid = threadIdx.x;
    const float* xr = X + (size_t)row * cols;

    __shared__ float red[256];
    float m = 0.f;
    for (int k = tid; k < cols; k += 256) m = fmaxf(m, fabsf(xr[k]));
    red[tid] = m;
    __syncthreads();
    for (int w = 128; w > 0; w >>= 1) {
        if (tid < w) red[tid] = fmaxf(red[tid], red[tid + w]);
        __syncthreads();
    }
    m = red[0];
    const int e = (m > 0.f) ? (ilogbf(m) + 1) : 0;
    if (tid == 0) scale[row] = ldexpf(1.f, e - 6);

    const float u0   = ldexpf(1.f, e - 6);
    const float inv0 = ldexpf(1.f, 6 - e);

    for (int k = tid; k < cols; k += 256) {
        float r  = xr[k];
        float uu = u0, ii = inv0;
#pragma unroll
        for (int s = 0; s < NSLICE; s++) {
            const float q = rintf(__fmul_rn(r, ii));   // |q| <= 64
            S[(size_t)s * plane + (size_t)row * KPAD + k] = (int8_t)(int)q;
            r  = __fmaf_rn(-q, uu, r);                 // exact residual
            uu = __fmul_rn(uu, 0.0078125f);            // * 2^-7 (exact)
            ii = __fmul_rn(ii, 128.f);
        }
    }
    for (int k = cols + tid; k < KPAD; k += 256)
#pragma unroll
        for (int s = 0; s < NSLICE; s++)
            S[(size_t)s * plane + (size_t)row * KPAD + k] = 0;
}

// ---------------------------------------------------------------------------
// cp.async primitives
// ---------------------------------------------------------------------------
__device__ __forceinline__ void cp_async16(uint32_t saddr, const void* g)
{
    asm volatile("cp.async.cg.shared.global [%0], [%1], 16;"
                 :: "r"(saddr), "l"(g));
}
__device__ __forceinline__ void cp_commit()
{
    asm volatile("cp.async.commit_group;" ::: "memory");
}
template <int N>
__device__ __forceinline__ void cp_wait()
{
    asm volatile("cp.async.wait_group %0;" :: "n"(N) : "memory");
}

// ---------------------------------------------------------------------------
// Layer-1 EXACT-DOT GEMM on tensor cores (s8 mma, exact s32) — R15/R16 math,
// rebuilt pipeline: 2-stage cp.async smem double buffer (no register staging,
// no spills), grid n-major for L2 reuse of the A slices.
// Block 64x32, 8 warps (4m x 2n), warp tile 16x16. Diagonal-shared s32
// accumulators: |G_d| <= 5*784*64^2 < 2^24 so (float)G_d exact; TwoSum fold;
// exact power-of-2 rescale. z1 bit-identical to R15/R16.
// smem row stride 12 u32 (48B): conflict-free gather + 16B-aligned cp.async.
// ---------------------------------------------------------------------------
__device__ __forceinline__ void mma_s8(int* d, const uint32_t* a,
                                       const uint32_t* b)
{
    asm volatile(
        "mma.sync.aligned.m16n8k32.row.col.s32.s8.s8.s32 "
        "{%0,%1,%2,%3}, {%4,%5,%6,%7}, {%8,%9}, {%0,%1,%2,%3};"
        : "+r"(d[0]), "+r"(d[1]), "+r"(d[2]), "+r"(d[3])
        : "r"(a[0]), "r"(a[1]), "r"(a[2]), "r"(a[3]),
          "r"(b[0]), "r"(b[1]));
}

__global__ void __launch_bounds__(256, 2)
gemm1_imma(const int8_t* __restrict__ SX, const int8_t* __restrict__ SW,
           const float* __restrict__ su, const float* __restrict__ sv,
           float* __restrict__ C)
{
    // 2-stage smem: [stage][slice][row * 12 u32] (A: 64 rows, B: 32 rows)
    __shared__ uint32_t As[2][NSLICE][64 * 12];   // 30.7 KB
    __shared__ uint32_t Bs[2][NSLICE][32 * 12];   // 15.4 KB

    const int tid  = threadIdx.x;
    const int warp = tid >> 5;
    const int lane = tid & 31;
    const int g    = lane >> 2;     // 0..7
    const int tg   = lane & 3;      // 0..3
    const int wm   = warp >> 1;     // 0..3  (16 rows each)
    const int wn   = warp & 1;      // 0..1  (16 cols each)
    const int m0   = blockIdx.y * 64;   // n-major grid: y = m tile
    const int n0   = blockIdx.x * 32;   //               x = n tile

    const size_t planeA = (size_t)MROWS * KPAD;
    const size_t planeB = (size_t)H * KPAD;

    int acc[NSLICE][2][4];          // [diagonal][n-frag][reg], exact s32
#pragma unroll
    for (int d = 0; d < NSLICE; d++)
#pragma unroll
        for (int nf = 0; nf < 2; nf++)
#pragma unroll
            for (int r = 0; r < 4; r++) acc[d][nf][r] = 0;

    // Issue all cp.async for one chunk into one stage (960 x 16B, <=4/thread)
    auto issue = [&](int kc, int stg) {
        const int k0 = kc * 32;
#pragma unroll
        for (int u = 0; u < 4; u++) {
            const int idx = tid + u * 256;
            if (idx < 640) {                       // A: 5 slices x 64 rows x 2
                const int s   = idx >> 7;
                const int rem = idx & 127;
                const int row = rem >> 1;
                const int q   = rem & 1;
                uint32_t dst = (uint32_t)__cvta_generic_to_shared(
                    &As[stg][s][row * 12 + q * 4]);
                cp_async16(dst, SX + (size_t)s * planeA
                                  + (size_t)(m0 + row) * KPAD + k0 + q * 16);
            } else if (idx < 960) {                // B: 5 slices x 32 rows x 2
                const int j   = idx - 640;
                const int s   = j >> 6;
                const int rem = j & 63;
                const int row = rem >> 1;
                const int q   = rem & 1;
                uint32_t dst = (uint32_t)__cvta_generic_to_shared(
                    &Bs[stg][s][row * 12 + q * 4]);
                cp_async16(dst, SW + (size_t)s * planeB
                                  + (size_t)(n0 + row) * KPAD + k0 + q * 16);
            }
        }
    };

    // Prologue: stage 0 <- chunk 0
    issue(0, 0);
    cp_commit();

    for (int kc = 0; kc < NCHUNK; kc++) {
        const int p = kc & 1;
        // Overlap: issue chunk kc+1 into the other stage (safe: that stage
        // was last computed at kc-1; all threads passed the barrier below).
        if (kc + 1 < NCHUNK) {
            issue(kc + 1, p ^ 1);
            cp_commit();
            cp_wait<1>();          // chunk kc complete, kc+1 in flight
        } else {
            cp_wait<0>();          // last chunk complete
        }
        __syncthreads();

        // Gather fragments from stage p
        uint32_t af[NSLICE][4];
        const int r0 = wm * 16 + g;
#pragma unroll
        for (int s = 0; s < NSLICE; s++) {
            af[s][0] = As[p][s][r0 * 12 + tg];
            af[s][1] = As[p][s][(r0 + 8) * 12 + tg];
            af[s][2] = As[p][s][r0 * 12 + tg + 4];
            af[s][3] = As[p][s][(r0 + 8) * 12 + tg + 4];
        }
        uint32_t bf[NSLICE][2][2];
#pragma unroll
        for (int s = 0; s < NSLICE; s++)
#pragma unroll
            for (int nf = 0; nf < 2; nf++) {
                const int cb = wn * 16 + nf * 8 + g;
                bf[s][nf][0] = Bs[p][s][cb * 12 + tg];
                bf[s][nf][1] = Bs[p][s][cb * 12 + tg + 4];
            }

        // 15 slice pairs -> 5 diagonal accumulators (exact s32)
#pragma unroll
        for (int s = 0; s < NSLICE; s++)
#pragma unroll
            for (int t = 0; t + s < NSLICE; t++)
#pragma unroll
                for (int nf = 0; nf < 2; nf++)
                    mma_s8(acc[s + t][nf], af[s], bf[t][nf]);

        __syncthreads();   // all warps done with stage p before it's refilled
    }

    // Epilogue: fold diagonals (TwoSum, proven), exact rescale, store.
    const float PW[NSLICE] = { 1.f, 0.0078125f, 6.103515625e-5f,
                               4.76837158203125e-7f,
                               3.7252902984619140625e-9f };
#pragma unroll
    for (int nf = 0; nf < 2; nf++) {
#pragma unroll
        for (int rr = 0; rr < 2; rr++) {
#pragma unroll
            for (int cc = 0; cc < 2; cc++) {
                const int reg = rr * 2 + cc;
                float s = 0.f, c = 0.f;
#pragma unroll
                for (int d = 0; d < NSLICE; d++) {
                    const float term =
                        __fmul_rn((float)acc[d][nf][reg], PW[d]);
                    const float t   = __fadd_rn(s, term);
                    const float bb  = __fsub_rn(t, s);
                    const float err = __fadd_rn(
                        __fsub_rn(s, __fsub_rn(t, bb)),
                        __fsub_rn(term, bb));
                    s = t;
                    c = __fadd_rn(c, err);
                }
                const int row = m0 + wm * 16 + g + 8 * rr;
                const int col = n0 + wn * 16 + nf * 8 + tg * 2 + cc;
                const float val = __fadd_rn(s, c);
                const float sc  = __fmul_rn(__ldg(su + row), __ldg(sv + col));
                C[(size_t)row * H + col] = __fmul_rn(val, sc);
            }
        }
    }
}

// ---------------------------------------------------------------------------
// SERIAL-FP32 GEMM (layer 2) — strict ascending-k fp32 FMA chain from 0 per
// output (bit-exact class, proven R9-R16). 8x10 micro-tile (BM=128, BN=160).
// ---------------------------------------------------------------------------
__global__ void __launch_bounds__(256)
gemm_nt_f32(const float* __restrict__ A, const float* __restrict__ Bw,
            float* __restrict__ C, int M, int N, int K)
{
    __shared__ float As[16][129];
    __shared__ float Bs[16][161];

    const int tid = threadIdx.x;
    const int tx  = tid & 15;
    const int ty  = tid >> 4;
    const int m0  = blockIdx.x * 128;
    const int n0  = blockIdx.y * 160;

    float acc[8][10];
#pragma unroll
    for (int i = 0; i < 8; i++)
#pragma unroll
        for (int j = 0; j < 10; j++) acc[i][j] = 0.f;

    for (int k0 = 0; k0 < K; k0 += 16) {
#pragma unroll
        for (int j = tid; j < 512; j += 256) {
            int row = j >> 2;
            int c4  = (j & 3) << 2;
            float4 v = *reinterpret_cast<const float4*>(
                A + (size_t)(m0 + row) * K + k0 + c4);
            As[c4 + 0][row] = v.x;
            As[c4 + 1][row] = v.y;
            As[c4 + 2][row] = v.z;
            As[c4 + 3][row] = v.w;
        }
#pragma unroll
        for (int j = tid; j < 640; j += 256) {
            int row = j >> 2;
            int c4  = (j & 3) << 2;
            float4 v = *reinterpret_cast<const float4*>(
                Bw + (size_t)(n0 + row) * K + k0 + c4);
            Bs[c4 + 0][row] = v.x;
            Bs[c4 + 1][row] = v.y;
            Bs[c4 + 2][row] = v.z;
            Bs[c4 + 3][row] = v.w;
        }
        __syncthreads();

#pragma unroll
        for (int kk = 0; kk < 16; kk++) {   // strict ascending-k chain
            float a[8], b[10];
#pragma unroll
            for (int i = 0; i < 8; i++) a[i] = As[kk][ty * 8 + i];
#pragma unroll
            for (int j = 0; j < 10; j++) b[j] = Bs[kk][tx * 10 + j];
#pragma unroll
            for (int i = 0; i < 8; i++)
#pragma unroll
                for (int j = 0; j < 10; j++)
                    acc[i][j] = fmaf(a[i], b[j], acc[i][j]);
        }
        __syncthreads();
    }

#pragma unroll
    for (int i = 0; i < 8; i++) {
        const int r = m0 + ty * 8 + i;
#pragma unroll
        for (int j = 0; j < 10; j++)
            C[(size_t)r * N + n0 + tx * 10 + j] = acc[i][j];
    }
}

// ---------------------------------------------------------------------------
// Skinny exact-dot GEMM (layer 3) via fp32 Dot2 — proven exact (R12-R16).
// ---------------------------------------------------------------------------
__global__ void __launch_bounds__(640)
gemm3_df32(const float* __restrict__ A, const float* __restrict__ W3,
           float* __restrict__ Cz)
{
    __shared__ float As[64][81];
    const int tid  = threadIdx.x;
    const int r    = tid & 63;
    const int o    = tid >> 6;          // 0..9
    const int row0 = blockIdx.x * 64;

    float s = 0.f, c = 0.f;
    for (int k0 = 0; k0 < 800; k0 += 80) {
        for (int j = tid; j < 1280; j += 640) {
            int rr = j / 20;
            int cc = (j % 20) * 4;
            float4 v = *reinterpret_cast<const float4*>(
                A + (size_t)(row0 + rr) * 800 + k0 + cc);
            As[rr][cc + 0] = v.x;
            As[rr][cc + 1] = v.y;
            As[rr][cc + 2] = v.z;
            As[rr][cc + 3] = v.w;
        }
        __syncthreads();
        const float* w = W3 + (size_t)o * 800 + k0;
#pragma unroll
        for (int k = 0; k < 80; k++) {
            const float a = As[r][k];
            const float b = __ldg(w + k);
            const float p  = __fmul_rn(a, b);
            const float ep = __fmaf_rn(a, b, -p);
            const float t   = __fadd_rn(s, p);
            const float bb  = __fsub_rn(t, s);
            const float err = __fadd_rn(
                __fsub_rn(s, __fsub_rn(t, bb)),
                __fsub_rn(p, bb));
            s = t;
            c = __fadd_rn(c, __fadd_rn(err, ep));
        }
        __syncthreads();
    }
    Cz[(size_t)(row0 + r) * OUT + o] = __fadd_rn(s, c);
}

// ---------------------------------------------------------------------------
// LIF scans — EXACT associations proven in R9-R16 (rel_err = 0). Do not change.
// ---------------------------------------------------------------------------
template <int ORDER>
__global__ void __launch_bounds__(256)
scan_hidden(const float* __restrict__ z, const float* __restrict__ bias,
            const float* __restrict__ thr, float* __restrict__ spk_out)
{
    const int idx = blockIdx.x * blockDim.x + threadIdx.x;
    if (idx >= BH) return;
    const int h = idx % H;
    const float bv = bias[h];
    const float tv = thr[h];
    float m = 0.f;
#pragma unroll
    for (int t = 0; t < T; t++) {
        const float zv = z[(size_t)t * BH + idx];
        float mnew;
        if (ORDER == 1) {
            const float xt = __fadd_rn(zv, bv);
            mnew = __fadd_rn(__fmul_rn(BETA, m), xt);
        } else {
            mnew = __fadd_rn(__fadd_rn(__fmul_rn(BETA, m), zv), bv);
        }
        const bool fire = (mnew > tv);
        spk_out[(size_t)t * BH + idx] = fire ? 1.f : 0.f;
        m = fire ? 0.f : mnew;
    }
}

__global__ void __launch_bounds__(256)
scan_out(const float* __restrict__ z3, const float* __restrict__ b3,
         float* __restrict__ s3, float* __restrict__ sum_out)
{
    const int idx = blockIdx.x * blockDim.x + threadIdx.x;
    if (idx >= BO) return;
    const int o = idx % OUT;
    const float bv = b3[o];
    float m = 0.f, sum = 0.f;
#pragma unroll
    for (int t = 0; t < T; t++) {
        const float zv = z3[(size_t)t * BO + idx];
        const float mnew = __fadd_rn(__fadd_rn(__fmul_rn(BETA, m), zv), bv);
        const bool fire = (mnew > 1.0f);
        const float s = fire ? 1.f : 0.f;
        s3[(size_t)t * BO + idx] = s;
        sum = __fadd_rn(sum, s);
        m = fire ? 0.f : mnew;
    }
    sum_out[idx] = sum;
}

// ---------------------------------------------------------------------------
// kernel_launch — graph-capturable, allocation-free.
// Inputs: x, W1, b1, W2, b2, W3, b3, thresh1, thresh2
// Outputs: sum[512,10], s1r[50,512,800], s2r[50,512,800], s3r[50,512,10]
// ---------------------------------------------------------------------------
extern "C" void kernel_launch(void* const* d_in, const int* in_sizes, int n_in,
                              void* d_out, int out_size)
{
    const float* x    = (const float*)d_in[0];
    const float* W1   = (const float*)d_in[1];
    const float* b1   = (const float*)d_in[2];
    const float* W2   = (const float*)d_in[3];
    const float* b2   = (const float*)d_in[4];
    const float* W3   = (const float*)d_in[5];
    const float* b3   = (const float*)d_in[6];
    const float* thr1 = (const float*)d_in[7];
    const float* thr2 = (const float*)d_in[8];

    float* out     = (float*)d_out;
    float* out_sum = out;                                  // [512,10]
    float* s1      = out + (size_t)BO;                     // [50,512,800]
    float* s2      = s1 + (size_t)T * BH;                  // [50,512,800]
    float* s3      = s2 + (size_t)T * BH;                  // [50,512,10]

    void *px1, *pz2, *pz3, *psx, *psw, *psu, *psv;
    cudaGetSymbolAddress(&px1, g_x1);
    cudaGetSymbolAddress(&pz2, g_z2);
    cudaGetSymbolAddress(&pz3, g_z3);
    cudaGetSymbolAddress(&psx, g_sx);
    cudaGetSymbolAddress(&psw, g_sw);
    cudaGetSymbolAddress(&psu, g_su);
    cudaGetSymbolAddress(&psv, g_sv);

    // 1) Slice x and W1 into 5 int8 planes (exact; K zero-padded to 800)
    slice_rows<<<MROWS, 256>>>(x, (int8_t*)psx, (float*)psu, IN,
                               (size_t)MROWS * KPAD);
    slice_rows<<<H, 256>>>(W1, (int8_t*)psw, (float*)psv, IN,
                           (size_t)H * KPAD);

    // 2) x1 = exact-dot(x, W1^T) via s8 tensor-core mma (cp.async pipeline)
    {
        dim3 grid(H / 32, MROWS / 64);   // n-major: A tiles reused in L2
        gemm1_imma<<<grid, 256>>>((const int8_t*)psx, (const int8_t*)psw,
                                  (const float*)psu, (const float*)psv,
                                  (float*)px1);
    }
    // 3) layer-1 LIF scan -> spk1  [bit-exact]
    scan_hidden<1><<<(BH + 255) / 256, 256>>>((const float*)px1, b1, thr1, s1);

    // 4) z2 = serial-fp32(spk1 @ W2^T)  [bit-exact]
    {
        dim3 grid(MROWS / 128, H / 160);
        gemm_nt_f32<<<grid, 256>>>(s1, W2, (float*)pz2, MROWS, H, H);
    }
    // 5) layer-2 LIF scan -> spk2  [bit-exact]
    scan_hidden<2><<<(BH + 255) / 256, 256>>>((const float*)pz2, b2, thr2, s2);

    // 6) z3 = exact-dot(spk2, W3^T) — fp32 Dot2
    gemm3_df32<<<MROWS / 64, 640>>>(s2, W3, (float*)pz3);

    // 7) layer-3 LIF scan -> s3r + spike-count sum
    scan_out<<<(BO + 255) / 256, 256>>>((const float*)pz3, b3, s3, out_sum);
}